// round 1
// baseline (speedup 1.0000x reference)
#include <cuda_runtime.h>

#define HEADS 6
#define HD 32
#define CDIM 192
#define NQ 576
#define WSZ 8
#define DISP 4
#define IMG 256
#define BATCH 4
#define TOK 64
#define NWIN 1024
#define ATT_SCALE 0.17677669529663687f

// scratch (allocation-free rule: __device__ globals)
__device__ float g_qkv[(size_t)BATCH * HEADS * NWIN * 3 * TOK * HD]; // ~604MB
__device__ float g_attn[(size_t)BATCH * IMG * IMG * CDIM];            // ~201MB
__device__ float g_bias[TOK * TOK];

// ---------------------------------------------------------------------------
// Kernel 0: gather rel-pos bias table (64x64) from pos_embedding (15x15)
// ---------------------------------------------------------------------------
__global__ void bias_kernel(const float* __restrict__ pos) {
    int idx = blockIdx.x * blockDim.x + threadIdx.x;
    if (idx < TOK * TOK) {
        int i = idx >> 6, j = idx & 63;
        int ih = i >> 3, iw = i & 7;
        int jh = j >> 3, jw = j & 7;
        g_bias[idx] = pos[(ih - jh + 7) * 15 + (iw - jw + 7)];
    }
}

// ---------------------------------------------------------------------------
// Kernel 1: QKV GEMM.  C[m, o] = sum_c x_rolled[m, c] * w_qkv[o, c]
// M = 262144 (b*y*x in rolled coords), N = 576, K = 192.
// Tile 64x64, K-chunks of 64. 256 threads, 4x4 per thread.
// Output scattered into window-partitioned layout:
//   g_qkv[(((bb*6+head)*1024 + win)*3 + s)*64*32 + t*32 + d]
// ---------------------------------------------------------------------------
__global__ __launch_bounds__(256) void qkv_gemm(const float* __restrict__ x,
                                                const float* __restrict__ wqkv) {
    __shared__ float As[64 * 68];  // [m][k] padded
    __shared__ float Bs[64 * 68];  // [k][n] padded (transposed)

    int m0 = blockIdx.y * 64;
    int n0 = blockIdx.x * 64;
    int tid = threadIdx.x;
    int tx = tid & 15, ty = tid >> 4;

    float acc[4][4] = {};

    for (int kb = 0; kb < CDIM; kb += 64) {
        // Load A tile: 64 rows x 64 cols, coalesced float4, roll folded in.
        #pragma unroll
        for (int l = 0; l < 4; l++) {
            int idx4 = tid + l * 256;           // 0..1023
            int r = idx4 >> 4, c4 = idx4 & 15;
            int m = m0 + r;
            int bb = m >> 16;
            int y = (m >> 8) & 255, xx = m & 255;
            int ys = (y + DISP) & 255, xs = (xx + DISP) & 255;
            float4 v = *(const float4*)(x + ((size_t)((bb * IMG + ys) * IMG + xs)) * CDIM + kb + c4 * 4);
            *(float4*)(As + r * 68 + c4 * 4) = v;
        }
        // Load B tile transposed: Bs[k][n].
        #pragma unroll
        for (int l = 0; l < 4; l++) {
            int idx4 = tid + l * 256;
            int o = idx4 & 63, c4 = idx4 >> 6;  // c4 = 0..15
            float4 v = *(const float4*)(wqkv + (size_t)(n0 + o) * CDIM + kb + c4 * 4);
            Bs[(c4 * 4 + 0) * 68 + o] = v.x;
            Bs[(c4 * 4 + 1) * 68 + o] = v.y;
            Bs[(c4 * 4 + 2) * 68 + o] = v.z;
            Bs[(c4 * 4 + 3) * 68 + o] = v.w;
        }
        __syncthreads();

        #pragma unroll 8
        for (int k = 0; k < 64; k++) {
            float4 bv = *(const float4*)(Bs + k * 68 + tx * 4);
            float a0 = As[(ty * 4 + 0) * 68 + k];
            float a1 = As[(ty * 4 + 1) * 68 + k];
            float a2 = As[(ty * 4 + 2) * 68 + k];
            float a3 = As[(ty * 4 + 3) * 68 + k];
            acc[0][0] += a0 * bv.x; acc[0][1] += a0 * bv.y; acc[0][2] += a0 * bv.z; acc[0][3] += a0 * bv.w;
            acc[1][0] += a1 * bv.x; acc[1][1] += a1 * bv.y; acc[1][2] += a1 * bv.z; acc[1][3] += a1 * bv.w;
            acc[2][0] += a2 * bv.x; acc[2][1] += a2 * bv.y; acc[2][2] += a2 * bv.z; acc[2][3] += a2 * bv.w;
            acc[3][0] += a3 * bv.x; acc[3][1] += a3 * bv.y; acc[3][2] += a3 * bv.z; acc[3][3] += a3 * bv.w;
        }
        __syncthreads();
    }

    // Scatter store into window-partitioned qkv buffer.
    // o..o+3 are contiguous in d (n0 multiple of 64, tx*4 stays within a 32-run).
    int o = n0 + tx * 4;
    int s = o / CDIM;
    int rem = o - s * CDIM;
    int head = rem >> 5;
    int d = rem & 31;
    #pragma unroll
    for (int i = 0; i < 4; i++) {
        int m = m0 + ty * 4 + i;
        int bb = m >> 16;
        int y = (m >> 8) & 255, xx = m & 255;
        int win = (y >> 3) * 32 + (xx >> 3);
        int t = (y & 7) * 8 + (xx & 7);
        size_t addr = ((((size_t)(bb * HEADS + head) * NWIN + win) * 3 + s) * TOK + t) * HD + d;
        *(float4*)(g_qkv + addr) = make_float4(acc[i][0], acc[i][1], acc[i][2], acc[i][3]);
    }
}

// ---------------------------------------------------------------------------
// Kernel 2: per-(b,head,window) attention. 64 threads, thread = one query row.
// ---------------------------------------------------------------------------
__global__ __launch_bounds__(64) void attn_kernel() {
    __shared__ float ks[TOK * HD];
    __shared__ float vs[TOK * HD];
    __shared__ float bs[TOK * 65];  // padded for conflict-free row reads

    int bid = blockIdx.x;
    int win = bid & (NWIN - 1);
    int hb = bid >> 10;              // 0..23
    int head = hb % HEADS;
    int bb = hb / HEADS;
    int tid = threadIdx.x;           // query row i

    size_t base = ((size_t)((bb * HEADS + head) * NWIN + win)) * 3 * TOK * HD;
    const float* qp = g_qkv + base;
    const float* kp = qp + TOK * HD;
    const float* vp = kp + TOK * HD;

    // Load K and V tiles (512 float4 each), coalesced.
    for (int idx = tid; idx < TOK * HD / 4; idx += 64) {
        *(float4*)(ks + idx * 4) = *(const float4*)(kp + idx * 4);
        *(float4*)(vs + idx * 4) = *(const float4*)(vp + idx * 4);
    }
    // Load bias table into padded smem.
    for (int idx = tid; idx < TOK * TOK / 4; idx += 64) {
        float4 v = *(const float4*)(g_bias + idx * 4);
        int i = (idx * 4) >> 6;
        int j = (idx * 4) & 63;
        float* dst = bs + i * 65 + j;
        dst[0] = v.x; dst[1] = v.y; dst[2] = v.z; dst[3] = v.w;
    }

    // My q row in registers.
    float qv[HD];
    #pragma unroll
    for (int d4 = 0; d4 < 8; d4++) {
        float4 v = *(const float4*)(qp + tid * HD + d4 * 4);
        qv[d4 * 4 + 0] = v.x; qv[d4 * 4 + 1] = v.y;
        qv[d4 * 4 + 2] = v.z; qv[d4 * 4 + 3] = v.w;
    }
    __syncthreads();

    // Scores (fully unrolled so sc[] stays in registers).
    float sc[TOK];
    float mx = -1e30f;
    #pragma unroll
    for (int j = 0; j < TOK; j++) {
        float a = 0.f;
        #pragma unroll
        for (int d4 = 0; d4 < 8; d4++) {
            float4 kv = *(const float4*)(ks + j * HD + d4 * 4);
            a += qv[d4 * 4 + 0] * kv.x + qv[d4 * 4 + 1] * kv.y
               + qv[d4 * 4 + 2] * kv.z + qv[d4 * 4 + 3] * kv.w;
        }
        a = a * ATT_SCALE + bs[tid * 65 + j];
        sc[j] = a;
        mx = fmaxf(mx, a);
    }

    float sum = 0.f;
    #pragma unroll
    for (int j = 0; j < TOK; j++) {
        float e = __expf(sc[j] - mx);
        sc[j] = e;
        sum += e;
    }
    float inv = 1.f / sum;

    float ov[HD];
    #pragma unroll
    for (int d = 0; d < HD; d++) ov[d] = 0.f;
    #pragma unroll
    for (int j = 0; j < TOK; j++) {
        float p = sc[j] * inv;
        #pragma unroll
        for (int d4 = 0; d4 < 8; d4++) {
            float4 vv = *(const float4*)(vs + j * HD + d4 * 4);
            ov[d4 * 4 + 0] += p * vv.x; ov[d4 * 4 + 1] += p * vv.y;
            ov[d4 * 4 + 2] += p * vv.z; ov[d4 * 4 + 3] += p * vv.w;
        }
    }

    // Un-window write: [b, y, x, head*32+d] in rolled coords.
    int wy = win >> 5, wx = win & 31;
    int y = wy * 8 + (tid >> 3);
    int xx = wx * 8 + (tid & 7);
    float* op = g_attn + ((size_t)(bb * IMG + y) * IMG + xx) * CDIM + head * HD;
    #pragma unroll
    for (int d4 = 0; d4 < 8; d4++)
        *(float4*)(op + d4 * 4) =
            make_float4(ov[d4 * 4], ov[d4 * 4 + 1], ov[d4 * 4 + 2], ov[d4 * 4 + 3]);
}

// ---------------------------------------------------------------------------
// Kernel 3: output projection + bias, roll-back folded into the store.
// out[m, o] = sum_c g_attn[m, c] * w_out[o, c] + b_out[o]
// ---------------------------------------------------------------------------
__global__ __launch_bounds__(256) void out_gemm(const float* __restrict__ wout,
                                                const float* __restrict__ bout,
                                                float* __restrict__ out) {
    __shared__ float As[64 * 68];
    __shared__ float Bs[64 * 68];

    int m0 = blockIdx.y * 64;
    int n0 = blockIdx.x * 64;
    int tid = threadIdx.x;
    int tx = tid & 15, ty = tid >> 4;

    float acc[4][4] = {};

    for (int kb = 0; kb < CDIM; kb += 64) {
        #pragma unroll
        for (int l = 0; l < 4; l++) {
            int idx4 = tid + l * 256;
            int r = idx4 >> 4, c4 = idx4 & 15;
            float4 v = *(const float4*)(g_attn + (size_t)(m0 + r) * CDIM + kb + c4 * 4);
            *(float4*)(As + r * 68 + c4 * 4) = v;
        }
        #pragma unroll
        for (int l = 0; l < 4; l++) {
            int idx4 = tid + l * 256;
            int o = idx4 & 63, c4 = idx4 >> 6;
            float4 v = *(const float4*)(wout + (size_t)(n0 + o) * CDIM + kb + c4 * 4);
            Bs[(c4 * 4 + 0) * 68 + o] = v.x;
            Bs[(c4 * 4 + 1) * 68 + o] = v.y;
            Bs[(c4 * 4 + 2) * 68 + o] = v.z;
            Bs[(c4 * 4 + 3) * 68 + o] = v.w;
        }
        __syncthreads();

        #pragma unroll 8
        for (int k = 0; k < 64; k++) {
            float4 bv = *(const float4*)(Bs + k * 68 + tx * 4);
            float a0 = As[(ty * 4 + 0) * 68 + k];
            float a1 = As[(ty * 4 + 1) * 68 + k];
            float a2 = As[(ty * 4 + 2) * 68 + k];
            float a3 = As[(ty * 4 + 3) * 68 + k];
            acc[0][0] += a0 * bv.x; acc[0][1] += a0 * bv.y; acc[0][2] += a0 * bv.z; acc[0][3] += a0 * bv.w;
            acc[1][0] += a1 * bv.x; acc[1][1] += a1 * bv.y; acc[1][2] += a1 * bv.z; acc[1][3] += a1 * bv.w;
            acc[2][0] += a2 * bv.x; acc[2][1] += a2 * bv.y; acc[2][2] += a2 * bv.z; acc[2][3] += a2 * bv.w;
            acc[3][0] += a3 * bv.x; acc[3][1] += a3 * bv.y; acc[3][2] += a3 * bv.z; acc[3][3] += a3 * bv.w;
        }
        __syncthreads();
    }

    int o = n0 + tx * 4;
    float4 bias = *(const float4*)(bout + o);
    #pragma unroll
    for (int i = 0; i < 4; i++) {
        int m = m0 + ty * 4 + i;
        int bb = m >> 16;
        int y = (m >> 8) & 255, xx = m & 255;
        int yf = (y + DISP) & 255, xf = (xx + DISP) & 255;
        float4 r = make_float4(acc[i][0] + bias.x, acc[i][1] + bias.y,
                               acc[i][2] + bias.z, acc[i][3] + bias.w);
        *(float4*)(out + ((size_t)(bb * IMG + yf) * IMG + xf) * CDIM + o) = r;
    }
}

// ---------------------------------------------------------------------------
extern "C" void kernel_launch(void* const* d_in, const int* in_sizes, int n_in,
                              void* d_out, int out_size) {
    const float* x    = (const float*)d_in[0];
    const float* wqkv = (const float*)d_in[1];
    const float* pos  = (const float*)d_in[2];
    const float* wout = (const float*)d_in[3];
    const float* bout = (const float*)d_in[4];
    float* out = (float*)d_out;

    bias_kernel<<<16, 256>>>(pos);
    qkv_gemm<<<dim3(NQ / 64, (BATCH * IMG * IMG) / 64), 256>>>(x, wqkv);
    attn_kernel<<<BATCH * HEADS * NWIN, 64>>>();
    out_gemm<<<dim3(CDIM / 64, (BATCH * IMG * IMG) / 64), 256>>>(wout, bout, out);
}

// round 4
// speedup vs baseline: 2.0258x; 2.0258x over previous
#include <cuda_runtime.h>
#include <cstdint>

#define HEADS 6
#define HD 32
#define CDIM 192
#define NQ 576
#define DISP 4
#define IMG 256
#define BATCH 4
#define TOK 64
#define NWIN 1024
#define MTOT (BATCH * IMG * IMG)
#define ATT_SCALE 0.17677669529663687f

// scratch (allocation-free rule: __device__ globals)
__device__ float g_qkv[(size_t)MTOT * NQ];     // ROLLED coords, [m, 576]
__device__ float g_attn[(size_t)MTOT * CDIM];  // ROLLED coords, [m, 192]
__device__ float g_bias[TOK * TOK];

// ---------------------------------------------------------------------------
// mma.sync helpers (HMMA path — compiles for compute_103)
// ---------------------------------------------------------------------------
__device__ __forceinline__ uint32_t f2tf32(float f) {
    uint32_t r;
    asm("cvt.rna.tf32.f32 %0, %1;" : "=r"(r) : "f"(f));
    return r;
}
__device__ __forceinline__ void mma_tf32(float* c, const uint32_t* a, const uint32_t* b) {
    asm volatile(
        "mma.sync.aligned.m16n8k8.row.col.f32.tf32.tf32.f32 "
        "{%0,%1,%2,%3}, {%4,%5,%6,%7}, {%8,%9}, {%0,%1,%2,%3};"
        : "+f"(c[0]), "+f"(c[1]), "+f"(c[2]), "+f"(c[3])
        : "r"(a[0]), "r"(a[1]), "r"(a[2]), "r"(a[3]), "r"(b[0]), "r"(b[1]));
}

#define AST 196                       // smem row stride (fp32 words)
#define A_WORDS (128 * AST)
#define B_WORDS (64 * AST)
#define SMEM_BYTES ((A_WORDS + B_WORDS) * 4)

// ---------------------------------------------------------------------------
// Kernel 0: gather rel-pos bias table
// ---------------------------------------------------------------------------
__global__ void bias_kernel(const float* __restrict__ pos) {
    int idx = blockIdx.x * blockDim.x + threadIdx.x;
    if (idx < TOK * TOK) {
        int i = idx >> 6, j = idx & 63;
        g_bias[idx] = pos[((i >> 3) - (j >> 3) + 7) * 15 + ((i & 7) - (j & 7) + 7)];
    }
}

// ---------------------------------------------------------------------------
// Kernel 1: QKV GEMM (mma.sync tf32).  Roll folded into the A-load, so
// g_qkv is indexed by ROLLED coordinates.
// ---------------------------------------------------------------------------
__global__ __launch_bounds__(256) void qkv_tc(const float* __restrict__ x,
                                              const float* __restrict__ wqkv) {
    extern __shared__ uint32_t sm[];
    uint32_t* As = sm;            // [128][196] tf32 bits
    uint32_t* Bs = sm + A_WORDS;  // [64][196]

    int tid = threadIdx.x;
    int wid = tid >> 5, lane = tid & 31;
    int warp_m = (wid >> 1) * 32;
    int warp_n = (wid & 1) * 32;
    int lr = lane >> 2, lc = lane & 3;
    int m0 = blockIdx.x * 128;

    // Load A tile once (roll folded in), cvt to tf32.
    for (int i = tid; i < 6144; i += 256) {
        int r = i / 48, c4 = i % 48;
        int m = m0 + r;
        int bb = m >> 16, y = (m >> 8) & 255, xx = m & 255;
        int ys = (y + DISP) & 255, xs = (xx + DISP) & 255;
        float4 v = *(const float4*)(x + ((size_t)((bb * IMG + ys) * IMG + xs)) * CDIM + c4 * 4);
        uint4 t = make_uint4(f2tf32(v.x), f2tf32(v.y), f2tf32(v.z), f2tf32(v.w));
        *(uint4*)&As[r * AST + c4 * 4] = t;
    }

    for (int t = 0; t < 9; t++) {
        int n0 = t * 64;
        __syncthreads();
        for (int i = tid; i < 3072; i += 256) {
            int r = i / 48, c4 = i % 48;
            float4 v = *(const float4*)(wqkv + (size_t)(n0 + r) * CDIM + c4 * 4);
            uint4 tt = make_uint4(f2tf32(v.x), f2tf32(v.y), f2tf32(v.z), f2tf32(v.w));
            *(uint4*)&Bs[r * AST + c4 * 4] = tt;
        }
        __syncthreads();

        float acc[2][4][4] = {};
        #pragma unroll
        for (int k0 = 0; k0 < CDIM; k0 += 8) {
            uint32_t a[2][4], b[4][2];
            #pragma unroll
            for (int mt = 0; mt < 2; mt++) {
                int row = warp_m + mt * 16 + lr;
                a[mt][0] = As[row * AST + k0 + lc];
                a[mt][1] = As[(row + 8) * AST + k0 + lc];
                a[mt][2] = As[row * AST + k0 + lc + 4];
                a[mt][3] = As[(row + 8) * AST + k0 + lc + 4];
            }
            #pragma unroll
            for (int nt = 0; nt < 4; nt++) {
                int col = warp_n + nt * 8 + lr;
                b[nt][0] = Bs[col * AST + k0 + lc];
                b[nt][1] = Bs[col * AST + k0 + lc + 4];
            }
            #pragma unroll
            for (int mt = 0; mt < 2; mt++)
                #pragma unroll
                for (int nt = 0; nt < 4; nt++)
                    mma_tf32(acc[mt][nt], a[mt], b[nt]);
        }

        #pragma unroll
        for (int mt = 0; mt < 2; mt++) {
            size_t r0 = (size_t)(m0 + warp_m + mt * 16 + lr) * NQ + n0 + warp_n;
            size_t r1 = r0 + 8 * NQ;
            #pragma unroll
            for (int nt = 0; nt < 4; nt++) {
                int col = nt * 8 + lc * 2;
                *(float2*)(g_qkv + r0 + col) = make_float2(acc[mt][nt][0], acc[mt][nt][1]);
                *(float2*)(g_qkv + r1 + col) = make_float2(acc[mt][nt][2], acc[mt][nt][3]);
            }
        }
    }
}

// ---------------------------------------------------------------------------
// Kernel 2: windowed attention. g_qkv is ALREADY in rolled coords — gather
// windows at direct coordinates (NO extra DISP — that was the round-3 bug).
// ---------------------------------------------------------------------------
__global__ __launch_bounds__(64) void attn_kernel() {
    __shared__ float ks[TOK * HD];
    __shared__ float vs[TOK * HD];
    __shared__ float bs[TOK * 65];

    int bid = blockIdx.x;
    int win = bid & (NWIN - 1);
    int hb = bid >> 10;
    int head = hb % HEADS;
    int bb = hb / HEADS;
    int tid = threadIdx.x;
    int wy = win >> 5, wx = win & 31;

    #pragma unroll
    for (int it = 0; it < 8; it++) {
        int j = it * 8 + (tid >> 3);
        int ys = wy * 8 + (j >> 3);
        int xs = wx * 8 + (j & 7);
        size_t src = ((size_t)((bb * IMG + ys) * IMG + xs)) * NQ + head * HD + (tid & 7) * 4;
        *(float4*)(ks + j * HD + (tid & 7) * 4) = *(const float4*)(g_qkv + CDIM + src);
        *(float4*)(vs + j * HD + (tid & 7) * 4) = *(const float4*)(g_qkv + 2 * CDIM + src);
    }
    for (int idx = tid; idx < TOK * TOK / 4; idx += 64) {
        float4 v = *(const float4*)(g_bias + idx * 4);
        int i = (idx * 4) >> 6, j = (idx * 4) & 63;
        float* dst = bs + i * 65 + j;
        dst[0] = v.x; dst[1] = v.y; dst[2] = v.z; dst[3] = v.w;
    }

    float qv[HD];
    {
        int ys = wy * 8 + (tid >> 3);
        int xs = wx * 8 + (tid & 7);
        const float* qp = g_qkv + ((size_t)((bb * IMG + ys) * IMG + xs)) * NQ + head * HD;
        #pragma unroll
        for (int d4 = 0; d4 < 8; d4++) {
            float4 v = *(const float4*)(qp + d4 * 4);
            qv[d4 * 4] = v.x; qv[d4 * 4 + 1] = v.y; qv[d4 * 4 + 2] = v.z; qv[d4 * 4 + 3] = v.w;
        }
    }
    __syncthreads();

    float sc[TOK];
    float mx = -1e30f;
    #pragma unroll
    for (int j = 0; j < TOK; j++) {
        float a = 0.f;
        #pragma unroll
        for (int d4 = 0; d4 < 8; d4++) {
            float4 kv = *(const float4*)(ks + j * HD + d4 * 4);
            a += qv[d4 * 4] * kv.x + qv[d4 * 4 + 1] * kv.y
               + qv[d4 * 4 + 2] * kv.z + qv[d4 * 4 + 3] * kv.w;
        }
        a = a * ATT_SCALE + bs[tid * 65 + j];
        sc[j] = a;
        mx = fmaxf(mx, a);
    }
    float sum = 0.f;
    #pragma unroll
    for (int j = 0; j < TOK; j++) { float e = __expf(sc[j] - mx); sc[j] = e; sum += e; }
    float inv = 1.f / sum;

    float ov[HD];
    #pragma unroll
    for (int d = 0; d < HD; d++) ov[d] = 0.f;
    #pragma unroll
    for (int j = 0; j < TOK; j++) {
        float p = sc[j] * inv;
        #pragma unroll
        for (int d4 = 0; d4 < 8; d4++) {
            float4 vv = *(const float4*)(vs + j * HD + d4 * 4);
            ov[d4 * 4] += p * vv.x; ov[d4 * 4 + 1] += p * vv.y;
            ov[d4 * 4 + 2] += p * vv.z; ov[d4 * 4 + 3] += p * vv.w;
        }
    }

    int y = wy * 8 + (tid >> 3);
    int xx = wx * 8 + (tid & 7);
    float* op = g_attn + ((size_t)(bb * IMG + y) * IMG + xx) * CDIM + head * HD;
    #pragma unroll
    for (int d4 = 0; d4 < 8; d4++)
        *(float4*)(op + d4 * 4) =
            make_float4(ov[d4 * 4], ov[d4 * 4 + 1], ov[d4 * 4 + 2], ov[d4 * 4 + 3]);
}

// ---------------------------------------------------------------------------
// Kernel 3: output projection (mma.sync tf32) + bias; roll-back on store.
// ---------------------------------------------------------------------------
__global__ __launch_bounds__(256) void out_tc(const float* __restrict__ wout,
                                              const float* __restrict__ bout,
                                              float* __restrict__ out) {
    extern __shared__ uint32_t sm[];
    uint32_t* As = sm;
    uint32_t* Bs = sm + A_WORDS;

    int tid = threadIdx.x;
    int wid = tid >> 5, lane = tid & 31;
    int warp_m = (wid >> 1) * 32;
    int warp_n = (wid & 1) * 32;
    int lr = lane >> 2, lc = lane & 3;
    int m0 = blockIdx.x * 128;

    for (int i = tid; i < 6144; i += 256) {
        int r = i / 48, c4 = i % 48;
        float4 v = *(const float4*)(g_attn + (size_t)(m0 + r) * CDIM + c4 * 4);
        uint4 t = make_uint4(f2tf32(v.x), f2tf32(v.y), f2tf32(v.z), f2tf32(v.w));
        *(uint4*)&As[r * AST + c4 * 4] = t;
    }

    for (int t = 0; t < 3; t++) {
        int n0 = t * 64;
        __syncthreads();
        for (int i = tid; i < 3072; i += 256) {
            int r = i / 48, c4 = i % 48;
            float4 v = *(const float4*)(wout + (size_t)(n0 + r) * CDIM + c4 * 4);
            uint4 tt = make_uint4(f2tf32(v.x), f2tf32(v.y), f2tf32(v.z), f2tf32(v.w));
            *(uint4*)&Bs[r * AST + c4 * 4] = tt;
        }
        __syncthreads();

        float acc[2][4][4] = {};
        #pragma unroll
        for (int k0 = 0; k0 < CDIM; k0 += 8) {
            uint32_t a[2][4], b[4][2];
            #pragma unroll
            for (int mt = 0; mt < 2; mt++) {
                int row = warp_m + mt * 16 + lr;
                a[mt][0] = As[row * AST + k0 + lc];
                a[mt][1] = As[(row + 8) * AST + k0 + lc];
                a[mt][2] = As[row * AST + k0 + lc + 4];
                a[mt][3] = As[(row + 8) * AST + k0 + lc + 4];
            }
            #pragma unroll
            for (int nt = 0; nt < 4; nt++) {
                int col = warp_n + nt * 8 + lr;
                b[nt][0] = Bs[col * AST + k0 + lc];
                b[nt][1] = Bs[col * AST + k0 + lc + 4];
            }
            #pragma unroll
            for (int mt = 0; mt < 2; mt++)
                #pragma unroll
                for (int nt = 0; nt < 4; nt++)
                    mma_tf32(acc[mt][nt], a[mt], b[nt]);
        }

        #pragma unroll
        for (int mt = 0; mt < 2; mt++) {
            #pragma unroll
            for (int half = 0; half < 2; half++) {
                int m = m0 + warp_m + mt * 16 + lr + half * 8;
                int bb = m >> 16, y = (m >> 8) & 255, xx = m & 255;
                int yf = (y + DISP) & 255, xf = (xx + DISP) & 255;
                float* op = out + ((size_t)(bb * IMG + yf) * IMG + xf) * CDIM + n0 + warp_n;
                #pragma unroll
                for (int nt = 0; nt < 4; nt++) {
                    int col = nt * 8 + lc * 2;
                    float b0 = bout[n0 + warp_n + col];
                    float b1 = bout[n0 + warp_n + col + 1];
                    *(float2*)(op + col) = make_float2(acc[mt][nt][half * 2] + b0,
                                                       acc[mt][nt][half * 2 + 1] + b1);
                }
            }
        }
    }
}

// ---------------------------------------------------------------------------
extern "C" void kernel_launch(void* const* d_in, const int* in_sizes, int n_in,
                              void* d_out, int out_size) {
    const float* x    = (const float*)d_in[0];
    const float* wqkv = (const float*)d_in[1];
    const float* pos  = (const float*)d_in[2];
    const float* wout = (const float*)d_in[3];
    const float* bout = (const float*)d_in[4];
    float* out = (float*)d_out;

    cudaFuncSetAttribute(qkv_tc, cudaFuncAttributeMaxDynamicSharedMemorySize, SMEM_BYTES);
    cudaFuncSetAttribute(out_tc, cudaFuncAttributeMaxDynamicSharedMemorySize, SMEM_BYTES);

    bias_kernel<<<16, 256>>>(pos);
    qkv_tc<<<MTOT / 128, 256, SMEM_BYTES>>>(x, wqkv);
    attn_kernel<<<BATCH * HEADS * NWIN, 64>>>();
    out_tc<<<MTOT / 128, 256, SMEM_BYTES>>>(wout, bout, out);
}